// round 13
// baseline (speedup 1.0000x reference)
#include <cuda_runtime.h>
#include <cuda_fp16.h>
#include <cstdint>

#define BATCH 8
#define NPTS 200000
#define CH 32
#define RES 128
#define NBINS (RES * RES)
#define NSEG (BATCH * 3)
#define EPSF 1e-5f

// f16 accumulator, layout (b, plane, bin, channel): one bin = 64B (32 halves).
// 24 * 16384 * 32 * 2B = 25.2 MB. Zero-initialized at module load; finalize
// self-cleans after each use, so no dedicated zeroing pass is needed.
__device__ __half2 g_accum[(size_t)NSEG * NBINS * (CH / 2)];
__device__ float g_cnt[NSEG * NBINS];

__device__ __forceinline__ void red_add_v4_f16x2(__half2* addr,
                                                 uint32_t a0, uint32_t a1,
                                                 uint32_t a2, uint32_t a3) {
    // One 16B RMW carrying 8 f16 channels (max legal red vector width).
    asm volatile("red.global.add.noftz.v4.f16x2 [%0], {%1,%2,%3,%4};"
                 :: "l"(addr), "r"(a0), "r"(a1), "r"(a2), "r"(a3)
                 : "memory");
}

__device__ __forceinline__ void red_add_f32(float* addr, float v) {
    asm volatile("red.global.add.f32 [%0], %1;"
                 :: "l"(addr), "f"(v)
                 : "memory");
}

__device__ __forceinline__ int to_bin(float v) {
    // Byte-identical to the validated Round-1 formula (matches JAX exactly).
    float t = (v + 1.0f) / 2.0f - 0.5f;
    t = t / (1.0f + EPSF) + 0.5f;
    t = fminf(fmaxf(t, 0.0f), 1.0f - EPSF);
    return (int)(t * 128.0f);
}

// Thread = point; coalesced strided channel loads;
// payload scatter via 4x v4.f16x2 RED per plane + 1 count RED.
__global__ void __launch_bounds__(256, 8)
scatter_kernel(const float* __restrict__ xyz,
               const float* __restrict__ feat) {
    int idx = blockIdx.x * blockDim.x + threadIdx.x;
    if (idx >= BATCH * NPTS) return;
    int b = idx / NPTS;
    int n = idx - b * NPTS;

    const float* p = xyz + (size_t)idx * 3;
    float x = p[0], y = p[1], z = p[2];
    int ix = to_bin(x);
    int iy = to_bin(y);
    int iz = to_bin(z);

    int bin_xy = ix + RES * iy;
    int bin_yz = iy + RES * iz;
    int bin_xz = ix + RES * iz;

    size_t base_b = (size_t)b * 3 * NBINS;
    red_add_f32(&g_cnt[base_b + 0 * NBINS + bin_xy], 1.0f);
    red_add_f32(&g_cnt[base_b + 1 * NBINS + bin_yz], 1.0f);
    red_add_f32(&g_cnt[base_b + 2 * NBINS + bin_xz], 1.0f);

    // Load 32 channels (coalesced across the warp), pack to 16 half2.
    const float* fb = feat + (size_t)b * CH * NPTS + n;
    uint32_t h[16];
#pragma unroll
    for (int k = 0; k < 16; k++) {
        float f0 = __ldg(fb + (size_t)(2 * k) * NPTS);
        float f1 = __ldg(fb + (size_t)(2 * k + 1) * NPTS);
        __half2 hh = __floats2half2_rn(f0, f1);
        h[k] = *reinterpret_cast<uint32_t*>(&hh);
    }

    __half2* a0 = g_accum + (base_b + (size_t)0 * NBINS + bin_xy) * (CH / 2);
    __half2* a1 = g_accum + (base_b + (size_t)1 * NBINS + bin_yz) * (CH / 2);
    __half2* a2 = g_accum + (base_b + (size_t)2 * NBINS + bin_xz) * (CH / 2);

#pragma unroll
    for (int q = 0; q < 4; q++)
        red_add_v4_f16x2(a0 + 4 * q, h[4 * q], h[4 * q + 1], h[4 * q + 2], h[4 * q + 3]);
#pragma unroll
    for (int q = 0; q < 4; q++)
        red_add_v4_f16x2(a1 + 4 * q, h[4 * q], h[4 * q + 1], h[4 * q + 2], h[4 * q + 3]);
#pragma unroll
    for (int q = 0; q < 4; q++)
        red_add_v4_f16x2(a2 + 4 * q, h[4 * q], h[4 * q + 1], h[4 * q + 2], h[4 * q + 3]);
}

// Transpose (bin, channel) -> (channel, bin) with count division, then
// SELF-CLEAN: zero exactly the accumulator/count bytes this block consumed,
// so the next graph replay starts from zeroed scratch with no zeroing pass.
// Block = 32x32, grid = (NBINS/32, 3, B).
__global__ void finalize_kernel(float* __restrict__ out) {
    __shared__ float tile[32][33];
    __shared__ float cnts[32];

    int pix0 = blockIdx.x * 32;
    int pl = blockIdx.y;
    int b = blockIdx.z;
    int tx = threadIdx.x;
    int ty = threadIdx.y;

    size_t base = ((size_t)b * 3 + pl) * NBINS;

    // load: 32 channels contiguous per bin row (64B per row, 2B per thread)
    __half* arow = reinterpret_cast<__half*>(g_accum + (base + pix0 + ty) * (CH / 2));
    tile[ty][tx] = __half2float(arow[tx]);
    if (ty == 0) cnts[tx] = g_cnt[base + pix0 + tx];
    __syncthreads();

    // Self-clean: each thread zeroes exactly what it read (smem holds copies).
    arow[tx] = __float2half(0.0f);
    if (ty == 0) g_cnt[base + pix0 + tx] = 0.0f;

    float cnt = fmaxf(cnts[tx], 1.0f);
    out[(((size_t)b * 3 + pl) * CH + ty) * NBINS + pix0 + tx] = tile[tx][ty] / cnt;
}

extern "C" void kernel_launch(void* const* d_in, const int* in_sizes, int n_in,
                              void* d_out, int out_size) {
    const float* xyz = (const float*)d_in[0];    // (B, N, 3)
    const float* feat = (const float*)d_in[1];   // (B, C, N)
    float* out = (float*)d_out;                  // (B, 3, C, R, R)

    int total = BATCH * NPTS;
    scatter_kernel<<<(total + 255) / 256, 256>>>(xyz, feat);

    dim3 fgrid(NBINS / 32, 3, BATCH);
    dim3 fblk(32, 32);
    finalize_kernel<<<fgrid, fblk>>>(out);
}

// round 14
// speedup vs baseline: 1.2317x; 1.2317x over previous
#include <cuda_runtime.h>
#include <cuda_fp16.h>
#include <cstdint>

#define BATCH 8
#define NPTS 200000
#define CH 32
#define RES 128
#define NBINS (RES * RES)
#define NSEG (BATCH * 3)
#define EPSF 1e-5f

// f16 accumulator, layout (b, plane, bin, channel): one bin = 64B (32 halves).
// 24 * 16384 * 32 * 2B = 25.2 MB. Zero-initialized at module load; finalize
// self-cleans (16B stores) after each use -> no dedicated zeroing pass.
__device__ __half2 g_accum[(size_t)NSEG * NBINS * (CH / 2)];
__device__ float g_cnt[NSEG * NBINS];

__device__ __forceinline__ void red_add_v4_f16x2(__half2* addr,
                                                 uint32_t a0, uint32_t a1,
                                                 uint32_t a2, uint32_t a3) {
    // One 16B RMW carrying 8 f16 channels (max legal red vector width).
    asm volatile("red.global.add.noftz.v4.f16x2 [%0], {%1,%2,%3,%4};"
                 :: "l"(addr), "r"(a0), "r"(a1), "r"(a2), "r"(a3)
                 : "memory");
}

__device__ __forceinline__ void red_add_f32(float* addr, float v) {
    asm volatile("red.global.add.f32 [%0], %1;"
                 :: "l"(addr), "f"(v)
                 : "memory");
}

__device__ __forceinline__ int to_bin(float v) {
    // Byte-identical to the validated Round-1 formula (matches JAX exactly).
    float t = (v + 1.0f) / 2.0f - 0.5f;
    t = t / (1.0f + EPSF) + 0.5f;
    t = fminf(fmaxf(t, 0.0f), 1.0f - EPSF);
    return (int)(t * 128.0f);
}

// R11-identical scatter: thread = point; coalesced strided channel loads;
// payload scatter via 4x v4.f16x2 RED per plane + 1 count RED.
__global__ void scatter_kernel(const float* __restrict__ xyz,
                               const float* __restrict__ feat) {
    int idx = blockIdx.x * blockDim.x + threadIdx.x;
    if (idx >= BATCH * NPTS) return;
    int b = idx / NPTS;
    int n = idx - b * NPTS;

    const float* p = xyz + (size_t)idx * 3;
    float x = p[0], y = p[1], z = p[2];
    int ix = to_bin(x);
    int iy = to_bin(y);
    int iz = to_bin(z);

    int bin_xy = ix + RES * iy;
    int bin_yz = iy + RES * iz;
    int bin_xz = ix + RES * iz;

    size_t base_b = (size_t)b * 3 * NBINS;
    red_add_f32(&g_cnt[base_b + 0 * NBINS + bin_xy], 1.0f);
    red_add_f32(&g_cnt[base_b + 1 * NBINS + bin_yz], 1.0f);
    red_add_f32(&g_cnt[base_b + 2 * NBINS + bin_xz], 1.0f);

    // Load 32 channels (coalesced across the warp), pack to 16 half2.
    const float* fb = feat + (size_t)b * CH * NPTS + n;
    uint32_t h[16];
#pragma unroll
    for (int k = 0; k < 16; k++) {
        float f0 = __ldg(fb + (size_t)(2 * k) * NPTS);
        float f1 = __ldg(fb + (size_t)(2 * k + 1) * NPTS);
        __half2 hh = __floats2half2_rn(f0, f1);
        h[k] = *reinterpret_cast<uint32_t*>(&hh);
    }

    __half2* a0 = g_accum + (base_b + (size_t)0 * NBINS + bin_xy) * (CH / 2);
    __half2* a1 = g_accum + (base_b + (size_t)1 * NBINS + bin_yz) * (CH / 2);
    __half2* a2 = g_accum + (base_b + (size_t)2 * NBINS + bin_xz) * (CH / 2);

#pragma unroll
    for (int q = 0; q < 4; q++)
        red_add_v4_f16x2(a0 + 4 * q, h[4 * q], h[4 * q + 1], h[4 * q + 2], h[4 * q + 3]);
#pragma unroll
    for (int q = 0; q < 4; q++)
        red_add_v4_f16x2(a1 + 4 * q, h[4 * q], h[4 * q + 1], h[4 * q + 2], h[4 * q + 3]);
#pragma unroll
    for (int q = 0; q < 4; q++)
        red_add_v4_f16x2(a2 + 4 * q, h[4 * q], h[4 * q + 1], h[4 * q + 2], h[4 * q + 3]);
}

// Transpose (bin, channel) -> (channel, bin) with count division, then
// self-clean with WIDE (16B) stores so the next replay sees zeroed scratch.
// Block = 32x32, grid = (NBINS/32, 3, B).
__global__ void finalize_kernel(float* __restrict__ out) {
    __shared__ float tile[32][33];
    __shared__ float cnts[32];

    int pix0 = blockIdx.x * 32;
    int pl = blockIdx.y;
    int b = blockIdx.z;
    int tx = threadIdx.x;
    int ty = threadIdx.y;

    size_t base = ((size_t)b * 3 + pl) * NBINS;

    // load: 32 channels contiguous per bin row (64B per row, 2B per thread)
    const __half* arow = reinterpret_cast<const __half*>(g_accum + (base + pix0 + ty) * (CH / 2));
    tile[ty][tx] = __half2float(__ldg(arow + tx));
    if (ty == 0) cnts[tx] = g_cnt[base + pix0 + tx];
    __syncthreads();

    // Self-clean with 16B stores: 4 threads per row zero the 64B accumulator
    // row; one warp zeroes the 32 counts (128B) via float4.
    uint4 z4 = make_uint4(0u, 0u, 0u, 0u);
    if (tx < 4)
        reinterpret_cast<uint4*>(g_accum + (base + pix0 + ty) * (CH / 2))[tx] = z4;
    if (ty == 1 && tx < 8)
        reinterpret_cast<float4*>(g_cnt + base + pix0)[tx] =
            make_float4(0.f, 0.f, 0.f, 0.f);

    float cnt = fmaxf(cnts[tx], 1.0f);
    out[(((size_t)b * 3 + pl) * CH + ty) * NBINS + pix0 + tx] = tile[tx][ty] / cnt;
}

extern "C" void kernel_launch(void* const* d_in, const int* in_sizes, int n_in,
                              void* d_out, int out_size) {
    const float* xyz = (const float*)d_in[0];    // (B, N, 3)
    const float* feat = (const float*)d_in[1];   // (B, C, N)
    float* out = (float*)d_out;                  // (B, 3, C, R, R)

    int total = BATCH * NPTS;
    scatter_kernel<<<(total + 255) / 256, 256>>>(xyz, feat);

    dim3 fgrid(NBINS / 32, 3, BATCH);
    dim3 fblk(32, 32);
    finalize_kernel<<<fgrid, fblk>>>(out);
}